// round 9
// baseline (speedup 1.0000x reference)
#include <cuda_runtime.h>
#include <cuda_bf16.h>
#include <mma.h>
#include <math.h>
#include <stdint.h>

using namespace nvcuda;

// Problem constants (fixed shapes from reference setup_inputs)
#define BSZ   2
#define SEQ   1024
#define DM    1024
#define DI    2048
#define NS    16
#define DTR   64
#define ROWS  (BSZ*SEQ)     // 2048
#define CHUNK_T 256
#define NC    (SEQ/CHUNK_T) // 4
#define XPW   96            // dt_rank + 2*n_state

// ---------------- scratch (device globals; no allocation allowed) ----------
__device__ float g_xr[ROWS * 2 * DI];   // in_proj output (raw, bias folded later)
__device__ float g_u[ROWS * DI];        // conv+silu output
__device__ float g_xp[ROWS * XPW];      // x_proj output (dlt | B | C)
__device__ float g_xpp[4 * ROWS * XPW]; // x_proj split-K partials
__device__ float g_delta[ROWS * DI];    // softplus(dt_proj)

// bf16 hi/lo split buffers
__device__ __nv_bfloat16 g_xh[ROWS * DM],  g_xl[ROWS * DM];      // x split
__device__ __nv_bfloat16 g_wih[2*DI * DM], g_wil[2*DI * DM];     // W_in split
__device__ __nv_bfloat16 g_gh[ROWS * DI],  g_gl[ROWS * DI];      // gated scan out
__device__ __nv_bfloat16 g_woh[DM * DI],   g_wol[DM * DI];       // W_out split

// ---------------- cp.async helpers ------------------------------------------
__device__ __forceinline__ uint32_t smem_u32(const void* p) {
    uint32_t a;
    asm("{ .reg .u64 t; cvta.to.shared.u64 t, %1; cvt.u32.u64 %0, t; }"
        : "=r"(a) : "l"(p));
    return a;
}
__device__ __forceinline__ void cp16(uint32_t dst, const void* src) {
    asm volatile("cp.async.cg.shared.global [%0], [%1], 16;" :: "r"(dst), "l"(src));
}
#define CP_COMMIT() asm volatile("cp.async.commit_group;" ::: "memory")
#define CP_WAIT(n)  asm volatile("cp.async.wait_group %0;" :: "n"(n) : "memory")

// ---------------- bf16 hi/lo split ------------------------------------------
__global__ __launch_bounds__(256)
void split_bf16(const float* __restrict__ src,
                __nv_bfloat16* __restrict__ hi,
                __nv_bfloat16* __restrict__ lo, int n)
{
    int i = blockIdx.x * blockDim.x + threadIdx.x;
    if (i < n) {
        float v = src[i];
        __nv_bfloat16 h = __float2bfloat16(v);
        hi[i] = h;
        lo[i] = __float2bfloat16(v - __bfloat162float(h));
    }
}

// ============ bf16x3 wmma GEMM, 3-stage cp.async, 1 sync/stage ===============
// C[M,N] = A[M,K] @ W[N,K]^T.  Block tile 128x128, BK=32, 256 thr (8 warps,
// 4 M x 2 N), warp tile 32x64.
#define BKP 40
extern __shared__ char dsm[];

template<int BN, int BLK>
__global__ void __launch_bounds__(BLK)
gemm3(const __nv_bfloat16* __restrict__ Ah, const __nv_bfloat16* __restrict__ Al,
      const __nv_bfloat16* __restrict__ Bh, const __nv_bfloat16* __restrict__ Bl,
      float* __restrict__ C, int N, int K)
{
    constexpr int OFF_AL   = 128 * BKP;                 // elem offsets
    constexpr int OFF_BH   = 256 * BKP;
    constexpr int OFF_BL   = (256 + BN) * BKP;
    constexpr int STAGE_E  = (256 + 2 * BN) * BKP;
    constexpr int STAGE_BY = STAGE_E * 2;

    const int tid = threadIdx.x;
    const int wid = tid >> 5;
    const int wr  = wid & 3;            // warp M row (32 rows)
    const int wc  = wid >> 2;           // warp N col (64 cols)
    const int m0  = blockIdx.y * 128;
    const int n0  = blockIdx.x * BN;

    const uint32_t sb0 = smem_u32(dsm);

    wmma::fragment<wmma::accumulator, 16, 16, 16, float> acc[2][4];
    #pragma unroll
    for (int i = 0; i < 2; i++)
        #pragma unroll
        for (int j = 0; j < 4; j++) wmma::fill_fragment(acc[i][j], 0.0f);

    // fill one stage: 16B chunks, 4 per row (32 bf16 of data, stride BKP)
    auto fill = [&](int buf, int k0) {
        uint32_t sb = sb0 + buf * STAGE_BY;
        #pragma unroll
        for (int id = tid; id < 512; id += BLK) {       // Ah/Al: 128 rows x 4
            int r = id >> 2, c = id & 3;
            const size_t go = (size_t)(m0 + r) * K + k0 + c * 8;
            uint32_t so = (uint32_t)(r * BKP + c * 8) * 2;
            cp16(sb + so, Ah + go);
            cp16(sb + OFF_AL * 2 + so, Al + go);
        }
        #pragma unroll
        for (int id = tid; id < BN * 4; id += BLK) {    // Bh/Bl: BN rows x 4
            int r = id >> 2, c = id & 3;
            const size_t go = (size_t)(n0 + r) * K + k0 + c * 8;
            uint32_t so = (uint32_t)(r * BKP + c * 8) * 2;
            cp16(sb + OFF_BH * 2 + so, Bh + go);
            cp16(sb + OFF_BL * 2 + so, Bl + go);
        }
    };

    const int S = K >> 5;
    fill(0, 0);  CP_COMMIT();
    fill(1, 32); CP_COMMIT();

    int cur = 0;
    for (int s = 0; s < S; s++) {
        if (s + 1 < S) CP_WAIT(1); else CP_WAIT(0);
        __syncthreads();
        // barrier orders all warps past compute(s-1); filling buffer
        // (s+2)%3 == (s-1)%3 afterwards is safe.
        if (s + 2 < S) { fill((s + 2) % 3, (s + 2) << 5); CP_COMMIT(); }

        const __nv_bfloat16* Sm = (const __nv_bfloat16*)(dsm + cur * STAGE_BY);

        #pragma unroll
        for (int kk = 0; kk < 32; kk += 16) {
            wmma::fragment<wmma::matrix_a, 16, 16, 16, __nv_bfloat16, wmma::row_major> ah[2], al[2];
            #pragma unroll
            for (int i = 0; i < 2; i++) {
                int r = (wr * 32 + i * 16) * BKP + kk;
                wmma::load_matrix_sync(ah[i], Sm + r, BKP);
                wmma::load_matrix_sync(al[i], Sm + OFF_AL + r, BKP);
            }
            #pragma unroll
            for (int j = 0; j < 4; j++) {
                wmma::fragment<wmma::matrix_b, 16, 16, 16, __nv_bfloat16, wmma::col_major> bh, bl;
                int r = (wc * 64 + j * 16) * BKP + kk;
                wmma::load_matrix_sync(bh, Sm + OFF_BH + r, BKP);
                wmma::load_matrix_sync(bl, Sm + OFF_BL + r, BKP);
                #pragma unroll
                for (int i = 0; i < 2; i++) {
                    wmma::mma_sync(acc[i][j], ah[i], bh, acc[i][j]);
                    wmma::mma_sync(acc[i][j], ah[i], bl, acc[i][j]);
                    wmma::mma_sync(acc[i][j], al[i], bh, acc[i][j]);
                }
            }
        }
        cur = (cur + 1) % 3;
    }

    #pragma unroll
    for (int i = 0; i < 2; i++)
        #pragma unroll
        for (int j = 0; j < 4; j++) {
            float* p = C + (size_t)(m0 + wr * 32 + i * 16) * N + n0 + wc * 64 + j * 16;
            wmma::store_matrix_sync(p, acc[i][j], N, wmma::mem_row_major);
        }
}

#define DSM128 (3 * (256 + 2 * 128) * BKP * 2)   // 122880 B

// ---------------- dt_proj: delta = softplus(xp[:, :64] @ W_dt^T + b_dt) ------
__global__ __launch_bounds__(256)
void gemm_dt(const float* __restrict__ A,   // xp, lda=XPW
             const float* __restrict__ W,   // W_dt [DI, 64]
             const float* __restrict__ bias,
             float* __restrict__ C)         // delta [ROWS, DI]
{
    __shared__ float As[64][65];
    __shared__ float Ws[64][65];

    const int tid = threadIdx.x;
    const int m0 = blockIdx.y * 64;
    const int n0 = blockIdx.x * 64;

    #pragma unroll
    for (int j = 0; j < 4; j++) {
        int id = tid + j * 256;
        int r = id >> 4, c4 = (id & 15) << 2;
        float4 va = *(const float4*)(A + (size_t)(m0 + r) * XPW + c4);
        As[c4 + 0][r] = va.x; As[c4 + 1][r] = va.y;
        As[c4 + 2][r] = va.z; As[c4 + 3][r] = va.w;
        float4 vw = *(const float4*)(W + (size_t)(n0 + r) * DTR + c4);
        Ws[c4 + 0][r] = vw.x; Ws[c4 + 1][r] = vw.y;
        Ws[c4 + 2][r] = vw.z; Ws[c4 + 3][r] = vw.w;
    }
    __syncthreads();

    const int tx = tid & 15;
    const int ty = tid >> 4;
    float acc[4][4];
    #pragma unroll
    for (int i = 0; i < 4; i++)
        #pragma unroll
        for (int j = 0; j < 4; j++) acc[i][j] = 0.f;

    #pragma unroll 8
    for (int k = 0; k < 64; k++) {
        float a[4], b[4];
        #pragma unroll
        for (int i = 0; i < 4; i++) a[i] = As[k][ty * 4 + i];
        #pragma unroll
        for (int j = 0; j < 4; j++) b[j] = Ws[k][tx * 4 + j];
        #pragma unroll
        for (int i = 0; i < 4; i++)
            #pragma unroll
            for (int j = 0; j < 4; j++)
                acc[i][j] = fmaf(a[i], b[j], acc[i][j]);
    }

    #pragma unroll
    for (int i = 0; i < 4; i++) {
        int m = m0 + ty * 4 + i;
        #pragma unroll
        for (int j = 0; j < 4; j++) {
            int n = n0 + tx * 4 + j;
            float v = acc[i][j] + bias[n];
            v = fmaxf(v, 0.f) + log1pf(expf(-fabsf(v)));
            C[(size_t)m * DI + n] = v;
        }
    }
}

// ---------------- skinny GEMM split-K: partials[ks] = u @ W_x^T --------------
__global__ __launch_bounds__(256)
void gemm_skinny(const float* __restrict__ A,
                 const float* __restrict__ W,
                 float* __restrict__ P)
{
    __shared__ float As[32][17];
    __shared__ float Ws[32][97];

    const int tid = threadIdx.x;
    const int tx = tid & 31;
    const int ty = tid >> 5;
    const int m0 = blockIdx.x * 16;
    const int kb = blockIdx.y * (DI / 4);
    float* C = P + (size_t)blockIdx.y * ROWS * XPW;

    float acc[2][3];
    #pragma unroll
    for (int i = 0; i < 2; i++)
        #pragma unroll
        for (int j = 0; j < 3; j++) acc[i][j] = 0.f;

    for (int k0 = kb; k0 < kb + DI / 4; k0 += 32) {
        if (tid < 128) {
            int row = tid >> 3;
            int kq  = (tid & 7) << 2;
            float4 v = *(const float4*)(A + (size_t)(m0 + row) * DI + k0 + kq);
            As[kq + 0][row] = v.x; As[kq + 1][row] = v.y;
            As[kq + 2][row] = v.z; As[kq + 3][row] = v.w;
        }
        #pragma unroll
        for (int i = 0; i < 3; i++) {
            int f   = tid + i * 256;
            int row = f >> 3;
            int kq  = (f & 7) << 2;
            float4 v = *(const float4*)(W + (size_t)row * DI + k0 + kq);
            Ws[kq + 0][row] = v.x; Ws[kq + 1][row] = v.y;
            Ws[kq + 2][row] = v.z; Ws[kq + 3][row] = v.w;
        }
        __syncthreads();

        #pragma unroll
        for (int k = 0; k < 32; k++) {
            float a0 = As[k][ty * 2 + 0], a1 = As[k][ty * 2 + 1];
            float b0 = Ws[k][tx * 3 + 0], b1 = Ws[k][tx * 3 + 1], b2 = Ws[k][tx * 3 + 2];
            acc[0][0] = fmaf(a0, b0, acc[0][0]); acc[0][1] = fmaf(a0, b1, acc[0][1]); acc[0][2] = fmaf(a0, b2, acc[0][2]);
            acc[1][0] = fmaf(a1, b0, acc[1][0]); acc[1][1] = fmaf(a1, b1, acc[1][1]); acc[1][2] = fmaf(a1, b2, acc[1][2]);
        }
        __syncthreads();
    }

    #pragma unroll
    for (int i = 0; i < 2; i++)
        #pragma unroll
        for (int j = 0; j < 3; j++)
            C[(size_t)(m0 + ty * 2 + i) * XPW + tx * 3 + j] = acc[i][j];
}

__global__ __launch_bounds__(256)
void reduce_xp(const float* __restrict__ P, float* __restrict__ xp)
{
    int i = blockIdx.x * blockDim.x + threadIdx.x;
    if (i < ROWS * XPW)
        xp[i] = P[i] + P[i + ROWS * XPW] + P[i + 2 * ROWS * XPW] + P[i + 3 * ROWS * XPW];
}

// ---------------- causal depthwise conv (k=3) + SiLU, float4 -----------------
__global__ __launch_bounds__(256)
void conv_silu(const float* __restrict__ xr,
               const float* __restrict__ b_in,
               const float* __restrict__ cw,
               const float* __restrict__ cb,
               float* __restrict__ u)
{
    int q   = blockIdx.x * blockDim.x + threadIdx.x;
    int d4  = (q << 2) & (DI - 1);
    int row = q >> 9;
    int l   = row & (SEQ - 1);
    const float* base = xr + (size_t)row * (2 * DI) + d4;
    float4 bin = *(const float4*)(b_in + d4);
    float4 cb4 = *(const float4*)(cb + d4);
    float4 c0 = *(const float4*)(base);
    float4 c1 = (l >= 1) ? *(const float4*)(base - 2 * DI) : make_float4(0, 0, 0, 0);
    float4 c2 = (l >= 2) ? *(const float4*)(base - 4 * DI) : make_float4(0, 0, 0, 0);
    float m1 = (l >= 1) ? 1.f : 0.f;
    float m2 = (l >= 2) ? 1.f : 0.f;

    float4 o;
    #pragma unroll
    for (int t = 0; t < 4; t++) {
        float w0 = cw[(d4 + t) * 3 + 0], w1 = cw[(d4 + t) * 3 + 1], w2 = cw[(d4 + t) * 3 + 2];
        float b  = ((const float*)&bin)[t];
        float x0 = ((const float*)&c0)[t] + b;
        float x1 = ((const float*)&c1)[t] + b;
        float x2 = ((const float*)&c2)[t] + b;
        float a = fmaf(w2, x0, ((const float*)&cb4)[t]);
        a = fmaf(w1 * m1, x1, a);
        a = fmaf(w0 * m2, x2, a);
        ((float*)&o)[t] = a / (1.f + __expf(-a));
    }
    *(float4*)(u + ((size_t)row * DI + d4)) = o;
}

// ---------------- chunked selective scan + gating, emits bf16 hi/lo ----------
__global__ __launch_bounds__(128)
void scan_kernel(const float* __restrict__ A_log,
                 const float* __restrict__ delta,
                 const float* __restrict__ u,
                 const float* __restrict__ xr,
                 const float* __restrict__ b_in,
                 const float* __restrict__ xp,
                 __nv_bfloat16* __restrict__ gh,
                 __nv_bfloat16* __restrict__ gl)
{
    const int bc = blockIdx.x;
    const int b  = bc / NC;
    const int c  = bc - b * NC;
    const int d  = blockIdx.y * 128 + threadIdx.x;
    const int row0 = b * SEQ + c * CHUNK_T;
    const float bres = b_in[DI + d];

    float Aa[NS], st[NS];
    #pragma unroll
    for (int n = 0; n < NS; n++) {
        Aa[n] = -expf(A_log[d * NS + n]);
        st[n] = 0.f;
    }

    __shared__ float Bs[16][NS];
    __shared__ float Cs[16][NS];

    for (int t0 = 0; t0 < CHUNK_T; t0 += 16) {
        __syncthreads();
        #pragma unroll
        for (int i = 0; i < 4; i++) {
            int e   = threadIdx.x + i * 128;
            int tl  = e >> 5;
            int rem = e & 31;
            float v = xp[(size_t)(row0 + t0 + tl) * XPW + DTR + rem];
            if (rem < NS) Bs[tl][rem]       = v;
            else          Cs[tl][rem - NS]  = v;
        }
        __syncthreads();

        #pragma unroll 4
        for (int tt = 0; tt < 16; tt++) {
            const int row = row0 + t0 + tt;
            float dv = delta[(size_t)row * DI + d];
            float uv = u[(size_t)row * DI + d];
            float rv = xr[(size_t)row * (2 * DI) + DI + d] + bres;
            float du = dv * uv;
            float y  = 0.f;
            #pragma unroll
            for (int n = 0; n < NS; n++) {
                float a = __expf(dv * Aa[n]);
                st[n] = fmaf(a, st[n], du * Bs[tt][n]);
                y     = fmaf(st[n], Cs[tt][n], y);
            }
            float gate = rv / (1.f + __expf(-rv));
            float v = y * gate;
            __nv_bfloat16 h = __float2bfloat16(v);
            size_t idx = (size_t)row * DI + d;
            gh[idx] = h;
            gl[idx] = __float2bfloat16(v - __bfloat162float(h));
        }
    }
}

// ---------------- final bias add --------------------------------------------
__global__ __launch_bounds__(256)
void add_bias(float* __restrict__ C, const float* __restrict__ b, int n)
{
    int i = blockIdx.x * blockDim.x + threadIdx.x;
    if (i < n) C[i] += b[i & (DM - 1)];
}

// ---------------- launch ----------------------------------------------------
extern "C" void kernel_launch(void* const* d_in, const int* in_sizes, int n_in,
                              void* d_out, int out_size)
{
    const float* x      = (const float*)d_in[0];
    const float* W_in   = (const float*)d_in[1];
    const float* b_in   = (const float*)d_in[2];
    const float* conv_w = (const float*)d_in[3];
    const float* conv_b = (const float*)d_in[4];
    const float* W_x    = (const float*)d_in[5];
    const float* W_dt   = (const float*)d_in[6];
    const float* b_dt   = (const float*)d_in[7];
    const float* A_log  = (const float*)d_in[8];
    const float* W_out  = (const float*)d_in[9];
    const float* b_out  = (const float*)d_in[10];
    float* out = (float*)d_out;

    float *xr, *u, *xp, *xpp, *delta;
    cudaGetSymbolAddress((void**)&xr,    g_xr);
    cudaGetSymbolAddress((void**)&u,     g_u);
    cudaGetSymbolAddress((void**)&xp,    g_xp);
    cudaGetSymbolAddress((void**)&xpp,   g_xpp);
    cudaGetSymbolAddress((void**)&delta, g_delta);

    __nv_bfloat16 *xh, *xl, *wih, *wil, *gh, *gl, *woh, *wol;
    cudaGetSymbolAddress((void**)&xh,  g_xh);
    cudaGetSymbolAddress((void**)&xl,  g_xl);
    cudaGetSymbolAddress((void**)&wih, g_wih);
    cudaGetSymbolAddress((void**)&wil, g_wil);
    cudaGetSymbolAddress((void**)&gh,  g_gh);
    cudaGetSymbolAddress((void**)&gl,  g_gl);
    cudaGetSymbolAddress((void**)&woh, g_woh);
    cudaGetSymbolAddress((void**)&wol, g_wol);

    static bool attr_done = false;
    if (!attr_done) {
        cudaFuncSetAttribute((const void*)gemm3<128, 256>,
                             cudaFuncAttributeMaxDynamicSharedMemorySize, DSM128);
        attr_done = true;
    }

    // 1-3) bf16 hi/lo splits (W_out split moved up: independent; also places
    //      the in_proj GEMM at the profiler's captured launch slot)
    split_bf16<<<(ROWS * DM + 255) / 256, 256>>>(x, xh, xl, ROWS * DM);
    split_bf16<<<(2 * DI * DM + 255) / 256, 256>>>(W_in, wih, wil, 2 * DI * DM);
    split_bf16<<<(DM * DI + 255) / 256, 256>>>(W_out, woh, wol, DM * DI);

    // 4) in_proj: xr_raw[2048,4096] = x @ W_in^T  (128x128 tiles, 3-stage)
    gemm3<128, 256><<<dim3(2 * DI / 128, ROWS / 128), 256, DSM128>>>(
        xh, xl, wih, wil, xr, 2 * DI, DM);

    // 5) depthwise causal conv (+b_in) + silu -> u
    conv_silu<<<(ROWS * DI / 4) / 256, 256>>>(xr, b_in, conv_w, conv_b, u);

    // 6-7) x_proj split-K: xp[2048,96] = u @ W_x^T
    gemm_skinny<<<dim3(ROWS / 16, 4), 256>>>(u, W_x, xpp);
    reduce_xp<<<(ROWS * XPW + 255) / 256, 256>>>(xpp, xp);

    // 8) dt_proj + softplus: delta = softplus(xp[:, :64] @ W_dt^T + b_dt)
    gemm_dt<<<dim3(DI / 64, ROWS / 64), 256>>>(xp, W_dt, b_dt, delta);

    // 9) chunked selective scan + gating -> bf16 hi/lo of y*silu(res)
    scan_kernel<<<dim3(BSZ * NC, DI / 128), 128>>>(A_log, delta, u, xr, b_in, xp, gh, gl);

    // 10-11) out_proj: out = g @ W_out^T + b_out
    gemm3<128, 256><<<dim3(DM / 128, ROWS / 128), 256, DSM128>>>(
        gh, gl, woh, wol, out, DM, DI);
    add_bias<<<(ROWS * DM + 255) / 256, 256>>>(out, b_out, ROWS * DM);
}

// round 10
// speedup vs baseline: 1.0570x; 1.0570x over previous
#include <cuda_runtime.h>
#include <cuda_bf16.h>
#include <mma.h>
#include <math.h>
#include <stdint.h>

using namespace nvcuda;

// Problem constants (fixed shapes from reference setup_inputs)
#define BSZ   2
#define SEQ   1024
#define DM    1024
#define DI    2048
#define NS    16
#define DTR   64
#define ROWS  (BSZ*SEQ)     // 2048
#define CHUNK_T 256
#define NC    (SEQ/CHUNK_T) // 4
#define XPW   96            // dt_rank + 2*n_state

// ---------------- scratch (device globals; no allocation allowed) ----------
__device__ float g_xr[ROWS * 2 * DI];   // in_proj output (raw, bias folded later)
__device__ float g_u[ROWS * DI];        // conv+silu output
__device__ float g_xp[ROWS * XPW];      // x_proj output (dlt | B | C)
__device__ float g_xpp[4 * ROWS * XPW]; // x_proj split-K partials
__device__ float g_delta[ROWS * DI];    // softplus(dt_proj)

// bf16 hi/lo split buffers
__device__ __nv_bfloat16 g_xh[ROWS * DM],  g_xl[ROWS * DM];      // x split
__device__ __nv_bfloat16 g_wih[2*DI * DM], g_wil[2*DI * DM];     // W_in split
__device__ __nv_bfloat16 g_gh[ROWS * DI],  g_gl[ROWS * DI];      // gated scan out
__device__ __nv_bfloat16 g_woh[DM * DI],   g_wol[DM * DI];       // W_out split

// ---------------- cp.async helpers ------------------------------------------
__device__ __forceinline__ uint32_t smem_u32(const void* p) {
    uint32_t a;
    asm("{ .reg .u64 t; cvta.to.shared.u64 t, %1; cvt.u32.u64 %0, t; }"
        : "=r"(a) : "l"(p));
    return a;
}
__device__ __forceinline__ void cp16(uint32_t dst, const void* src) {
    asm volatile("cp.async.cg.shared.global [%0], [%1], 16;" :: "r"(dst), "l"(src));
}
#define CP_COMMIT() asm volatile("cp.async.commit_group;" ::: "memory")
#define CP_WAIT(n)  asm volatile("cp.async.wait_group %0;" :: "n"(n) : "memory")

// ---------------- bf16 hi/lo split ------------------------------------------
__global__ __launch_bounds__(256)
void split_bf16(const float* __restrict__ src,
                __nv_bfloat16* __restrict__ hi,
                __nv_bfloat16* __restrict__ lo, int n)
{
    int i = blockIdx.x * blockDim.x + threadIdx.x;
    if (i < n) {
        float v = src[i];
        __nv_bfloat16 h = __float2bfloat16(v);
        hi[i] = h;
        lo[i] = __float2bfloat16(v - __bfloat162float(h));
    }
}

// ============ bf16x3 wmma GEMM, 2-stage cp.async, 2 CTAs/SM ==================
// C[M,N] = A[M,K] @ W[N,K]^T.  Block tile 128x128, BK=32, 256 thr (8 warps,
// 4 M x 2 N), warp tile 32x64.  __launch_bounds__(256,2) caps regs at 128 so
// two CTAs co-reside per SM (smem 81920B/CTA); the co-resident CTA hides
// barrier + LDSM latency (R9 profile: occ 12.4%, tensor 40%, issue 17.5%).
#define BKP 40
extern __shared__ char dsm[];

__global__ void __launch_bounds__(256, 2)
gemm3(const __nv_bfloat16* __restrict__ Ah, const __nv_bfloat16* __restrict__ Al,
      const __nv_bfloat16* __restrict__ Bh, const __nv_bfloat16* __restrict__ Bl,
      float* __restrict__ C, int N, int K)
{
    constexpr int OFF_AL   = 128 * BKP;                 // elem offsets
    constexpr int OFF_BH   = 256 * BKP;
    constexpr int OFF_BL   = 384 * BKP;
    constexpr int STAGE_BY = 512 * BKP * 2;             // 40960 B

    const int tid = threadIdx.x;
    const int wid = tid >> 5;
    const int wr  = wid & 3;            // warp M row (32 rows)
    const int wc  = wid >> 2;           // warp N col (64 cols)
    const int m0  = blockIdx.y * 128;
    const int n0  = blockIdx.x * 128;

    const uint32_t sb0 = smem_u32(dsm);

    wmma::fragment<wmma::accumulator, 16, 16, 16, float> acc[2][4];
    #pragma unroll
    for (int i = 0; i < 2; i++)
        #pragma unroll
        for (int j = 0; j < 4; j++) wmma::fill_fragment(acc[i][j], 0.0f);

    // fill one stage: 16B chunks, 4 per row (32 bf16 of data, stride BKP)
    auto fill = [&](int buf, int k0) {
        uint32_t sb = sb0 + buf * STAGE_BY;
        #pragma unroll
        for (int j = 0; j < 2; j++) {                   // 128 rows x 4 chunks
            int id = tid + j * 256;
            int r = id >> 2, c = id & 3;
            const size_t ga = (size_t)(m0 + r) * K + k0 + c * 8;
            const size_t gb = (size_t)(n0 + r) * K + k0 + c * 8;
            uint32_t so = (uint32_t)(r * BKP + c * 8) * 2;
            cp16(sb + so, Ah + ga);
            cp16(sb + OFF_AL * 2 + so, Al + ga);
            cp16(sb + OFF_BH * 2 + so, Bh + gb);
            cp16(sb + OFF_BL * 2 + so, Bl + gb);
        }
    };

    const int S = K >> 5;
    fill(0, 0);
    CP_COMMIT();

    for (int s = 0; s < S; s++) {
        const int cur = s & 1;
        if (s + 1 < S) { fill(cur ^ 1, (s + 1) << 5); CP_COMMIT(); CP_WAIT(1); }
        else           { CP_WAIT(0); }
        __syncthreads();

        const __nv_bfloat16* Sm = (const __nv_bfloat16*)(dsm + cur * STAGE_BY);

        #pragma unroll
        for (int kk = 0; kk < 32; kk += 16) {
            wmma::fragment<wmma::matrix_a, 16, 16, 16, __nv_bfloat16, wmma::row_major> ah[2], al[2];
            #pragma unroll
            for (int i = 0; i < 2; i++) {
                int r = (wr * 32 + i * 16) * BKP + kk;
                wmma::load_matrix_sync(ah[i], Sm + r, BKP);
                wmma::load_matrix_sync(al[i], Sm + OFF_AL + r, BKP);
            }
            #pragma unroll
            for (int j = 0; j < 4; j++) {
                wmma::fragment<wmma::matrix_b, 16, 16, 16, __nv_bfloat16, wmma::col_major> bh, bl;
                int r = (wc * 64 + j * 16) * BKP + kk;
                wmma::load_matrix_sync(bh, Sm + OFF_BH + r, BKP);
                wmma::load_matrix_sync(bl, Sm + OFF_BL + r, BKP);
                #pragma unroll
                for (int i = 0; i < 2; i++) {
                    wmma::mma_sync(acc[i][j], ah[i], bh, acc[i][j]);
                    wmma::mma_sync(acc[i][j], ah[i], bl, acc[i][j]);
                    wmma::mma_sync(acc[i][j], al[i], bh, acc[i][j]);
                }
            }
        }
        __syncthreads();
    }

    #pragma unroll
    for (int i = 0; i < 2; i++)
        #pragma unroll
        for (int j = 0; j < 4; j++) {
            float* p = C + (size_t)(m0 + wr * 32 + i * 16) * N + n0 + wc * 64 + j * 16;
            wmma::store_matrix_sync(p, acc[i][j], N, wmma::mem_row_major);
        }
}

#define DSM128 (2 * 512 * BKP * 2)   // 81920 B

// ---------------- dt_proj: delta = softplus(xp[:, :64] @ W_dt^T + b_dt) ------
__global__ __launch_bounds__(256)
void gemm_dt(const float* __restrict__ A,   // xp, lda=XPW
             const float* __restrict__ W,   // W_dt [DI, 64]
             const float* __restrict__ bias,
             float* __restrict__ C)         // delta [ROWS, DI]
{
    __shared__ float As[64][65];
    __shared__ float Ws[64][65];

    const int tid = threadIdx.x;
    const int m0 = blockIdx.y * 64;
    const int n0 = blockIdx.x * 64;

    #pragma unroll
    for (int j = 0; j < 4; j++) {
        int id = tid + j * 256;
        int r = id >> 4, c4 = (id & 15) << 2;
        float4 va = *(const float4*)(A + (size_t)(m0 + r) * XPW + c4);
        As[c4 + 0][r] = va.x; As[c4 + 1][r] = va.y;
        As[c4 + 2][r] = va.z; As[c4 + 3][r] = va.w;
        float4 vw = *(const float4*)(W + (size_t)(n0 + r) * DTR + c4);
        Ws[c4 + 0][r] = vw.x; Ws[c4 + 1][r] = vw.y;
        Ws[c4 + 2][r] = vw.z; Ws[c4 + 3][r] = vw.w;
    }
    __syncthreads();

    const int tx = tid & 15;
    const int ty = tid >> 4;
    float acc[4][4];
    #pragma unroll
    for (int i = 0; i < 4; i++)
        #pragma unroll
        for (int j = 0; j < 4; j++) acc[i][j] = 0.f;

    #pragma unroll 8
    for (int k = 0; k < 64; k++) {
        float a[4], b[4];
        #pragma unroll
        for (int i = 0; i < 4; i++) a[i] = As[k][ty * 4 + i];
        #pragma unroll
        for (int j = 0; j < 4; j++) b[j] = Ws[k][tx * 4 + j];
        #pragma unroll
        for (int i = 0; i < 4; i++)
            #pragma unroll
            for (int j = 0; j < 4; j++)
                acc[i][j] = fmaf(a[i], b[j], acc[i][j]);
    }

    #pragma unroll
    for (int i = 0; i < 4; i++) {
        int m = m0 + ty * 4 + i;
        #pragma unroll
        for (int j = 0; j < 4; j++) {
            int n = n0 + tx * 4 + j;
            float v = acc[i][j] + bias[n];
            v = fmaxf(v, 0.f) + log1pf(expf(-fabsf(v)));
            C[(size_t)m * DI + n] = v;
        }
    }
}

// ---------------- skinny GEMM split-K: partials[ks] = u @ W_x^T --------------
__global__ __launch_bounds__(256)
void gemm_skinny(const float* __restrict__ A,
                 const float* __restrict__ W,
                 float* __restrict__ P)
{
    __shared__ float As[32][17];
    __shared__ float Ws[32][97];

    const int tid = threadIdx.x;
    const int tx = tid & 31;
    const int ty = tid >> 5;
    const int m0 = blockIdx.x * 16;
    const int kb = blockIdx.y * (DI / 4);
    float* C = P + (size_t)blockIdx.y * ROWS * XPW;

    float acc[2][3];
    #pragma unroll
    for (int i = 0; i < 2; i++)
        #pragma unroll
        for (int j = 0; j < 3; j++) acc[i][j] = 0.f;

    for (int k0 = kb; k0 < kb + DI / 4; k0 += 32) {
        if (tid < 128) {
            int row = tid >> 3;
            int kq  = (tid & 7) << 2;
            float4 v = *(const float4*)(A + (size_t)(m0 + row) * DI + k0 + kq);
            As[kq + 0][row] = v.x; As[kq + 1][row] = v.y;
            As[kq + 2][row] = v.z; As[kq + 3][row] = v.w;
        }
        #pragma unroll
        for (int i = 0; i < 3; i++) {
            int f   = tid + i * 256;
            int row = f >> 3;
            int kq  = (f & 7) << 2;
            float4 v = *(const float4*)(W + (size_t)row * DI + k0 + kq);
            Ws[kq + 0][row] = v.x; Ws[kq + 1][row] = v.y;
            Ws[kq + 2][row] = v.z; Ws[kq + 3][row] = v.w;
        }
        __syncthreads();

        #pragma unroll
        for (int k = 0; k < 32; k++) {
            float a0 = As[k][ty * 2 + 0], a1 = As[k][ty * 2 + 1];
            float b0 = Ws[k][tx * 3 + 0], b1 = Ws[k][tx * 3 + 1], b2 = Ws[k][tx * 3 + 2];
            acc[0][0] = fmaf(a0, b0, acc[0][0]); acc[0][1] = fmaf(a0, b1, acc[0][1]); acc[0][2] = fmaf(a0, b2, acc[0][2]);
            acc[1][0] = fmaf(a1, b0, acc[1][0]); acc[1][1] = fmaf(a1, b1, acc[1][1]); acc[1][2] = fmaf(a1, b2, acc[1][2]);
        }
        __syncthreads();
    }

    #pragma unroll
    for (int i = 0; i < 2; i++)
        #pragma unroll
        for (int j = 0; j < 3; j++)
            C[(size_t)(m0 + ty * 2 + i) * XPW + tx * 3 + j] = acc[i][j];
}

__global__ __launch_bounds__(256)
void reduce_xp(const float* __restrict__ P, float* __restrict__ xp)
{
    int i = blockIdx.x * blockDim.x + threadIdx.x;
    if (i < ROWS * XPW)
        xp[i] = P[i] + P[i + ROWS * XPW] + P[i + 2 * ROWS * XPW] + P[i + 3 * ROWS * XPW];
}

// ---------------- causal depthwise conv (k=3) + SiLU, float4 -----------------
__global__ __launch_bounds__(256)
void conv_silu(const float* __restrict__ xr,
               const float* __restrict__ b_in,
               const float* __restrict__ cw,
               const float* __restrict__ cb,
               float* __restrict__ u)
{
    int q   = blockIdx.x * blockDim.x + threadIdx.x;
    int d4  = (q << 2) & (DI - 1);
    int row = q >> 9;
    int l   = row & (SEQ - 1);
    const float* base = xr + (size_t)row * (2 * DI) + d4;
    float4 bin = *(const float4*)(b_in + d4);
    float4 cb4 = *(const float4*)(cb + d4);
    float4 c0 = *(const float4*)(base);
    float4 c1 = (l >= 1) ? *(const float4*)(base - 2 * DI) : make_float4(0, 0, 0, 0);
    float4 c2 = (l >= 2) ? *(const float4*)(base - 4 * DI) : make_float4(0, 0, 0, 0);
    float m1 = (l >= 1) ? 1.f : 0.f;
    float m2 = (l >= 2) ? 1.f : 0.f;

    float4 o;
    #pragma unroll
    for (int t = 0; t < 4; t++) {
        float w0 = cw[(d4 + t) * 3 + 0], w1 = cw[(d4 + t) * 3 + 1], w2 = cw[(d4 + t) * 3 + 2];
        float b  = ((const float*)&bin)[t];
        float x0 = ((const float*)&c0)[t] + b;
        float x1 = ((const float*)&c1)[t] + b;
        float x2 = ((const float*)&c2)[t] + b;
        float a = fmaf(w2, x0, ((const float*)&cb4)[t]);
        a = fmaf(w1 * m1, x1, a);
        a = fmaf(w0 * m2, x2, a);
        ((float*)&o)[t] = a / (1.f + __expf(-a));
    }
    *(float4*)(u + ((size_t)row * DI + d4)) = o;
}

// ---------------- chunked selective scan + gating, emits bf16 hi/lo ----------
__global__ __launch_bounds__(128)
void scan_kernel(const float* __restrict__ A_log,
                 const float* __restrict__ delta,
                 const float* __restrict__ u,
                 const float* __restrict__ xr,
                 const float* __restrict__ b_in,
                 const float* __restrict__ xp,
                 __nv_bfloat16* __restrict__ gh,
                 __nv_bfloat16* __restrict__ gl)
{
    const int bc = blockIdx.x;
    const int b  = bc / NC;
    const int c  = bc - b * NC;
    const int d  = blockIdx.y * 128 + threadIdx.x;
    const int row0 = b * SEQ + c * CHUNK_T;
    const float bres = b_in[DI + d];

    float Aa[NS], st[NS];
    #pragma unroll
    for (int n = 0; n < NS; n++) {
        Aa[n] = -expf(A_log[d * NS + n]);
        st[n] = 0.f;
    }

    __shared__ float Bs[16][NS];
    __shared__ float Cs[16][NS];

    for (int t0 = 0; t0 < CHUNK_T; t0 += 16) {
        __syncthreads();
        #pragma unroll
        for (int i = 0; i < 4; i++) {
            int e   = threadIdx.x + i * 128;
            int tl  = e >> 5;
            int rem = e & 31;
            float v = xp[(size_t)(row0 + t0 + tl) * XPW + DTR + rem];
            if (rem < NS) Bs[tl][rem]       = v;
            else          Cs[tl][rem - NS]  = v;
        }
        __syncthreads();

        #pragma unroll 4
        for (int tt = 0; tt < 16; tt++) {
            const int row = row0 + t0 + tt;
            float dv = delta[(size_t)row * DI + d];
            float uv = u[(size_t)row * DI + d];
            float rv = xr[(size_t)row * (2 * DI) + DI + d] + bres;
            float du = dv * uv;
            float y  = 0.f;
            #pragma unroll
            for (int n = 0; n < NS; n++) {
                float a = __expf(dv * Aa[n]);
                st[n] = fmaf(a, st[n], du * Bs[tt][n]);
                y     = fmaf(st[n], Cs[tt][n], y);
            }
            float gate = rv / (1.f + __expf(-rv));
            float v = y * gate;
            __nv_bfloat16 h = __float2bfloat16(v);
            size_t idx = (size_t)row * DI + d;
            gh[idx] = h;
            gl[idx] = __float2bfloat16(v - __bfloat162float(h));
        }
    }
}

// ---------------- final bias add --------------------------------------------
__global__ __launch_bounds__(256)
void add_bias(float* __restrict__ C, const float* __restrict__ b, int n)
{
    int i = blockIdx.x * blockDim.x + threadIdx.x;
    if (i < n) C[i] += b[i & (DM - 1)];
}

// ---------------- launch ----------------------------------------------------
extern "C" void kernel_launch(void* const* d_in, const int* in_sizes, int n_in,
                              void* d_out, int out_size)
{
    const float* x      = (const float*)d_in[0];
    const float* W_in   = (const float*)d_in[1];
    const float* b_in   = (const float*)d_in[2];
    const float* conv_w = (const float*)d_in[3];
    const float* conv_b = (const float*)d_in[4];
    const float* W_x    = (const float*)d_in[5];
    const float* W_dt   = (const float*)d_in[6];
    const float* b_dt   = (const float*)d_in[7];
    const float* A_log  = (const float*)d_in[8];
    const float* W_out  = (const float*)d_in[9];
    const float* b_out  = (const float*)d_in[10];
    float* out = (float*)d_out;

    float *xr, *u, *xp, *xpp, *delta;
    cudaGetSymbolAddress((void**)&xr,    g_xr);
    cudaGetSymbolAddress((void**)&u,     g_u);
    cudaGetSymbolAddress((void**)&xp,    g_xp);
    cudaGetSymbolAddress((void**)&xpp,   g_xpp);
    cudaGetSymbolAddress((void**)&delta, g_delta);

    __nv_bfloat16 *xh, *xl, *wih, *wil, *gh, *gl, *woh, *wol;
    cudaGetSymbolAddress((void**)&xh,  g_xh);
    cudaGetSymbolAddress((void**)&xl,  g_xl);
    cudaGetSymbolAddress((void**)&wih, g_wih);
    cudaGetSymbolAddress((void**)&wil, g_wil);
    cudaGetSymbolAddress((void**)&gh,  g_gh);
    cudaGetSymbolAddress((void**)&gl,  g_gl);
    cudaGetSymbolAddress((void**)&woh, g_woh);
    cudaGetSymbolAddress((void**)&wol, g_wol);

    static bool attr_done = false;
    if (!attr_done) {
        cudaFuncSetAttribute((const void*)gemm3,
                             cudaFuncAttributeMaxDynamicSharedMemorySize, DSM128);
        attr_done = true;
    }

    // 1-3) bf16 hi/lo splits (W_out split early keeps gemm3 at profiler slot 4)
    split_bf16<<<(ROWS * DM + 255) / 256, 256>>>(x, xh, xl, ROWS * DM);
    split_bf16<<<(2 * DI * DM + 255) / 256, 256>>>(W_in, wih, wil, 2 * DI * DM);
    split_bf16<<<(DM * DI + 255) / 256, 256>>>(W_out, woh, wol, DM * DI);

    // 4) in_proj: xr_raw[2048,4096] = x @ W_in^T
    gemm3<<<dim3(2 * DI / 128, ROWS / 128), 256, DSM128>>>(
        xh, xl, wih, wil, xr, 2 * DI, DM);

    // 5) depthwise causal conv (+b_in) + silu -> u
    conv_silu<<<(ROWS * DI / 4) / 256, 256>>>(xr, b_in, conv_w, conv_b, u);

    // 6-7) x_proj split-K: xp[2048,96] = u @ W_x^T
    gemm_skinny<<<dim3(ROWS / 16, 4), 256>>>(u, W_x, xpp);
    reduce_xp<<<(ROWS * XPW + 255) / 256, 256>>>(xpp, xp);

    // 8) dt_proj + softplus: delta = softplus(xp[:, :64] @ W_dt^T + b_dt)
    gemm_dt<<<dim3(DI / 64, ROWS / 64), 256>>>(xp, W_dt, b_dt, delta);

    // 9) chunked selective scan + gating -> bf16 hi/lo of y*silu(res)
    scan_kernel<<<dim3(BSZ * NC, DI / 128), 128>>>(A_log, delta, u, xr, b_in, xp, gh, gl);

    // 10-11) out_proj: out = g @ W_out^T + b_out
    gemm3<<<dim3(DM / 128, ROWS / 128), 256, DSM128>>>(
        gh, gl, woh, wol, out, DM, DI);
    add_bias<<<(ROWS * DM + 255) / 256, 256>>>(out, b_out, ROWS * DM);
}

// round 11
// speedup vs baseline: 1.1250x; 1.0643x over previous
#include <cuda_runtime.h>
#include <cuda_bf16.h>
#include <mma.h>
#include <math.h>
#include <stdint.h>

using namespace nvcuda;

// Problem constants (fixed shapes from reference setup_inputs)
#define BSZ   2
#define SEQ   1024
#define DM    1024
#define DI    2048
#define NS    16
#define DTR   64
#define ROWS  (BSZ*SEQ)     // 2048
#define CHUNK_T 256
#define NC    (SEQ/CHUNK_T) // 4
#define XPW   96            // dt_rank + 2*n_state

// ---------------- scratch (device globals; no allocation allowed) ----------
__device__ float g_xr[ROWS * 2 * DI];   // in_proj output (raw, bias folded later)
__device__ float g_u[ROWS * DI];        // conv+silu output
__device__ float g_xp[ROWS * XPW];      // x_proj output (dlt | B | C)
__device__ float g_xpp[4 * ROWS * XPW]; // x_proj split-K partials
__device__ float g_delta[ROWS * DI];    // softplus(dt_proj)
__device__ float g_outp[2 * ROWS * DM]; // out_proj split-K partials

// bf16 hi/lo split buffers
__device__ __nv_bfloat16 g_xh[ROWS * DM],  g_xl[ROWS * DM];      // x split
__device__ __nv_bfloat16 g_wih[2*DI * DM], g_wil[2*DI * DM];     // W_in split
__device__ __nv_bfloat16 g_gh[ROWS * DI],  g_gl[ROWS * DI];      // gated scan out
__device__ __nv_bfloat16 g_woh[DM * DI],   g_wol[DM * DI];       // W_out split

// ---------------- cp.async helpers ------------------------------------------
__device__ __forceinline__ uint32_t smem_u32(const void* p) {
    uint32_t a;
    asm("{ .reg .u64 t; cvta.to.shared.u64 t, %1; cvt.u32.u64 %0, t; }"
        : "=r"(a) : "l"(p));
    return a;
}
__device__ __forceinline__ void cp16(uint32_t dst, const void* src) {
    asm volatile("cp.async.cg.shared.global [%0], [%1], 16;" :: "r"(dst), "l"(src));
}
#define CP_COMMIT() asm volatile("cp.async.commit_group;" ::: "memory")
#define CP_WAIT(n)  asm volatile("cp.async.wait_group %0;" :: "n"(n) : "memory")

// ---------------- fused bf16 hi/lo split (x, W_in, W_out in one launch) ------
#define QX  (ROWS * DM / 4)         // 524288 quads
#define QWI (2 * DI * DM / 4)       // 2097152 quads
#define QWO (DM * DI / 4)           // 524288 quads
#define QTOT (QX + QWI + QWO)

__global__ __launch_bounds__(256)
void fuse_split(const float* __restrict__ x,
                const float* __restrict__ Wi,
                const float* __restrict__ Wo,
                __nv_bfloat16* __restrict__ xh,  __nv_bfloat16* __restrict__ xl,
                __nv_bfloat16* __restrict__ wih, __nv_bfloat16* __restrict__ wil,
                __nv_bfloat16* __restrict__ woh, __nv_bfloat16* __restrict__ wol)
{
    int q = blockIdx.x * blockDim.x + threadIdx.x;
    if (q >= QTOT) return;

    const float* src;
    __nv_bfloat16 *dh, *dl;
    int local;
    if (q < QX)            { src = x;  dh = xh;  dl = xl;  local = q; }
    else if (q < QX + QWI) { src = Wi; dh = wih; dl = wil; local = q - QX; }
    else                   { src = Wo; dh = woh; dl = wol; local = q - QX - QWI; }

    float4 v = *(const float4*)(src + (size_t)local * 4);
    float f[4] = {v.x, v.y, v.z, v.w};
    __nv_bfloat16 h[4], l[4];
    #pragma unroll
    for (int t = 0; t < 4; t++) {
        h[t] = __float2bfloat16(f[t]);
        l[t] = __float2bfloat16(f[t] - __bfloat162float(h[t]));
    }
    __nv_bfloat162* ph = (__nv_bfloat162*)(dh + (size_t)local * 4);
    __nv_bfloat162* pl = (__nv_bfloat162*)(dl + (size_t)local * 4);
    ph[0] = __nv_bfloat162{h[0], h[1]};
    ph[1] = __nv_bfloat162{h[2], h[3]};
    pl[0] = __nv_bfloat162{l[0], l[1]};
    pl[1] = __nv_bfloat162{l[2], l[3]};
}

// ============ bf16x3 wmma GEMM, 2-stage cp.async, 2 CTAs/SM, split-K =========
// C[z][M,N] = A[M, kbase:kbase+Kslice] @ W[N, same]^T  (kbase = z*Kslice).
// Block tile 128x128, BK=32, 256 thr (8 warps, 4Mx2N), warp tile 32x64.
// __launch_bounds__(256,2): regs<=128 so 2 CTAs/SM (smem 81920B/CTA).
#define BKP 40
extern __shared__ char dsm[];

__global__ void __launch_bounds__(256, 2)
gemm3(const __nv_bfloat16* __restrict__ Ah, const __nv_bfloat16* __restrict__ Al,
      const __nv_bfloat16* __restrict__ Bh, const __nv_bfloat16* __restrict__ Bl,
      float* __restrict__ C, int N, int Kstride, int Kslice)
{
    constexpr int OFF_AL   = 128 * BKP;                 // elem offsets
    constexpr int OFF_BH   = 256 * BKP;
    constexpr int OFF_BL   = 384 * BKP;
    constexpr int STAGE_BY = 512 * BKP * 2;             // 40960 B

    const int tid = threadIdx.x;
    const int wid = tid >> 5;
    const int wr  = wid & 3;            // warp M row (32 rows)
    const int wc  = wid >> 2;           // warp N col (64 cols)
    const int m0  = blockIdx.y * 128;
    const int n0  = blockIdx.x * 128;
    const int kbase = blockIdx.z * Kslice;
    float* Cz = C + (size_t)blockIdx.z * ROWS * N;

    const uint32_t sb0 = smem_u32(dsm);

    wmma::fragment<wmma::accumulator, 16, 16, 16, float> acc[2][4];
    #pragma unroll
    for (int i = 0; i < 2; i++)
        #pragma unroll
        for (int j = 0; j < 4; j++) wmma::fill_fragment(acc[i][j], 0.0f);

    // fill one stage: 16B chunks, 4 per row (32 bf16 of data, stride BKP)
    auto fill = [&](int buf, int k0) {
        uint32_t sb = sb0 + buf * STAGE_BY;
        #pragma unroll
        for (int j = 0; j < 2; j++) {                   // 128 rows x 4 chunks
            int id = tid + j * 256;
            int r = id >> 2, c = id & 3;
            const size_t ga = (size_t)(m0 + r) * Kstride + kbase + k0 + c * 8;
            const size_t gb = (size_t)(n0 + r) * Kstride + kbase + k0 + c * 8;
            uint32_t so = (uint32_t)(r * BKP + c * 8) * 2;
            cp16(sb + so, Ah + ga);
            cp16(sb + OFF_AL * 2 + so, Al + ga);
            cp16(sb + OFF_BH * 2 + so, Bh + gb);
            cp16(sb + OFF_BL * 2 + so, Bl + gb);
        }
    };

    const int S = Kslice >> 5;
    fill(0, 0);
    CP_COMMIT();

    for (int s = 0; s < S; s++) {
        const int cur = s & 1;
        if (s + 1 < S) { fill(cur ^ 1, (s + 1) << 5); CP_COMMIT(); CP_WAIT(1); }
        else           { CP_WAIT(0); }
        __syncthreads();

        const __nv_bfloat16* Sm = (const __nv_bfloat16*)(dsm + cur * STAGE_BY);

        #pragma unroll
        for (int kk = 0; kk < 32; kk += 16) {
            wmma::fragment<wmma::matrix_a, 16, 16, 16, __nv_bfloat16, wmma::row_major> ah[2], al[2];
            #pragma unroll
            for (int i = 0; i < 2; i++) {
                int r = (wr * 32 + i * 16) * BKP + kk;
                wmma::load_matrix_sync(ah[i], Sm + r, BKP);
                wmma::load_matrix_sync(al[i], Sm + OFF_AL + r, BKP);
            }
            #pragma unroll
            for (int j = 0; j < 4; j++) {
                wmma::fragment<wmma::matrix_b, 16, 16, 16, __nv_bfloat16, wmma::col_major> bh, bl;
                int r = (wc * 64 + j * 16) * BKP + kk;
                wmma::load_matrix_sync(bh, Sm + OFF_BH + r, BKP);
                wmma::load_matrix_sync(bl, Sm + OFF_BL + r, BKP);
                #pragma unroll
                for (int i = 0; i < 2; i++) {
                    wmma::mma_sync(acc[i][j], ah[i], bh, acc[i][j]);
                    wmma::mma_sync(acc[i][j], ah[i], bl, acc[i][j]);
                    wmma::mma_sync(acc[i][j], al[i], bh, acc[i][j]);
                }
            }
        }
        __syncthreads();
    }

    #pragma unroll
    for (int i = 0; i < 2; i++)
        #pragma unroll
        for (int j = 0; j < 4; j++) {
            float* p = Cz + (size_t)(m0 + wr * 32 + i * 16) * N + n0 + wc * 64 + j * 16;
            wmma::store_matrix_sync(p, acc[i][j], N, wmma::mem_row_major);
        }
}

#define DSM128 (2 * 512 * BKP * 2)   // 81920 B

// ---------------- out_proj reduce (split-K sum) + bias -----------------------
__global__ __launch_bounds__(256)
void reduce_out(const float* __restrict__ P, const float* __restrict__ bias,
                float* __restrict__ out)
{
    int q = blockIdx.x * blockDim.x + threadIdx.x;   // quads over ROWS*DM/4
    if (q >= ROWS * DM / 4) return;
    int col4 = (q << 2) & (DM - 1);
    float4 a = *(const float4*)(P + (size_t)q * 4);
    float4 b = *(const float4*)(P + ROWS * DM + (size_t)q * 4);
    float4 c = *(const float4*)(bias + col4);
    float4 o = {a.x + b.x + c.x, a.y + b.y + c.y, a.z + b.z + c.z, a.w + b.w + c.w};
    *(float4*)(out + (size_t)q * 4) = o;
}

// ---------------- dt_proj: delta = softplus(xp[:, :64] @ W_dt^T + b_dt) ------
__global__ __launch_bounds__(256)
void gemm_dt(const float* __restrict__ A,   // xp, lda=XPW
             const float* __restrict__ W,   // W_dt [DI, 64]
             const float* __restrict__ bias,
             float* __restrict__ C)         // delta [ROWS, DI]
{
    __shared__ float As[64][65];
    __shared__ float Ws[64][65];

    const int tid = threadIdx.x;
    const int m0 = blockIdx.y * 64;
    const int n0 = blockIdx.x * 64;

    #pragma unroll
    for (int j = 0; j < 4; j++) {
        int id = tid + j * 256;
        int r = id >> 4, c4 = (id & 15) << 2;
        float4 va = *(const float4*)(A + (size_t)(m0 + r) * XPW + c4);
        As[c4 + 0][r] = va.x; As[c4 + 1][r] = va.y;
        As[c4 + 2][r] = va.z; As[c4 + 3][r] = va.w;
        float4 vw = *(const float4*)(W + (size_t)(n0 + r) * DTR + c4);
        Ws[c4 + 0][r] = vw.x; Ws[c4 + 1][r] = vw.y;
        Ws[c4 + 2][r] = vw.z; Ws[c4 + 3][r] = vw.w;
    }
    __syncthreads();

    const int tx = tid & 15;
    const int ty = tid >> 4;
    float acc[4][4];
    #pragma unroll
    for (int i = 0; i < 4; i++)
        #pragma unroll
        for (int j = 0; j < 4; j++) acc[i][j] = 0.f;

    #pragma unroll 8
    for (int k = 0; k < 64; k++) {
        float a[4], b[4];
        #pragma unroll
        for (int i = 0; i < 4; i++) a[i] = As[k][ty * 4 + i];
        #pragma unroll
        for (int j = 0; j < 4; j++) b[j] = Ws[k][tx * 4 + j];
        #pragma unroll
        for (int i = 0; i < 4; i++)
            #pragma unroll
            for (int j = 0; j < 4; j++)
                acc[i][j] = fmaf(a[i], b[j], acc[i][j]);
    }

    #pragma unroll
    for (int i = 0; i < 4; i++) {
        int m = m0 + ty * 4 + i;
        #pragma unroll
        for (int j = 0; j < 4; j++) {
            int n = n0 + tx * 4 + j;
            float v = acc[i][j] + bias[n];
            v = fmaxf(v, 0.f) + log1pf(expf(-fabsf(v)));
            C[(size_t)m * DI + n] = v;
        }
    }
}

// ---------------- skinny GEMM split-K: partials[ks] = u @ W_x^T --------------
__global__ __launch_bounds__(256)
void gemm_skinny(const float* __restrict__ A,
                 const float* __restrict__ W,
                 float* __restrict__ P)
{
    __shared__ float As[32][17];
    __shared__ float Ws[32][97];

    const int tid = threadIdx.x;
    const int tx = tid & 31;
    const int ty = tid >> 5;
    const int m0 = blockIdx.x * 16;
    const int kb = blockIdx.y * (DI / 4);
    float* C = P + (size_t)blockIdx.y * ROWS * XPW;

    float acc[2][3];
    #pragma unroll
    for (int i = 0; i < 2; i++)
        #pragma unroll
        for (int j = 0; j < 3; j++) acc[i][j] = 0.f;

    for (int k0 = kb; k0 < kb + DI / 4; k0 += 32) {
        if (tid < 128) {
            int row = tid >> 3;
            int kq  = (tid & 7) << 2;
            float4 v = *(const float4*)(A + (size_t)(m0 + row) * DI + k0 + kq);
            As[kq + 0][row] = v.x; As[kq + 1][row] = v.y;
            As[kq + 2][row] = v.z; As[kq + 3][row] = v.w;
        }
        #pragma unroll
        for (int i = 0; i < 3; i++) {
            int f   = tid + i * 256;
            int row = f >> 3;
            int kq  = (f & 7) << 2;
            float4 v = *(const float4*)(W + (size_t)row * DI + k0 + kq);
            Ws[kq + 0][row] = v.x; Ws[kq + 1][row] = v.y;
            Ws[kq + 2][row] = v.z; Ws[kq + 3][row] = v.w;
        }
        __syncthreads();

        #pragma unroll
        for (int k = 0; k < 32; k++) {
            float a0 = As[k][ty * 2 + 0], a1 = As[k][ty * 2 + 1];
            float b0 = Ws[k][tx * 3 + 0], b1 = Ws[k][tx * 3 + 1], b2 = Ws[k][tx * 3 + 2];
            acc[0][0] = fmaf(a0, b0, acc[0][0]); acc[0][1] = fmaf(a0, b1, acc[0][1]); acc[0][2] = fmaf(a0, b2, acc[0][2]);
            acc[1][0] = fmaf(a1, b0, acc[1][0]); acc[1][1] = fmaf(a1, b1, acc[1][1]); acc[1][2] = fmaf(a1, b2, acc[1][2]);
        }
        __syncthreads();
    }

    #pragma unroll
    for (int i = 0; i < 2; i++)
        #pragma unroll
        for (int j = 0; j < 3; j++)
            C[(size_t)(m0 + ty * 2 + i) * XPW + tx * 3 + j] = acc[i][j];
}

__global__ __launch_bounds__(256)
void reduce_xp(const float* __restrict__ P, float* __restrict__ xp)
{
    int i = blockIdx.x * blockDim.x + threadIdx.x;
    if (i < ROWS * XPW)
        xp[i] = P[i] + P[i + ROWS * XPW] + P[i + 2 * ROWS * XPW] + P[i + 3 * ROWS * XPW];
}

// ---------------- causal depthwise conv (k=3) + SiLU, float4 -----------------
__global__ __launch_bounds__(256)
void conv_silu(const float* __restrict__ xr,
               const float* __restrict__ b_in,
               const float* __restrict__ cw,
               const float* __restrict__ cb,
               float* __restrict__ u)
{
    int q   = blockIdx.x * blockDim.x + threadIdx.x;
    int d4  = (q << 2) & (DI - 1);
    int row = q >> 9;
    int l   = row & (SEQ - 1);
    const float* base = xr + (size_t)row * (2 * DI) + d4;
    float4 bin = *(const float4*)(b_in + d4);
    float4 cb4 = *(const float4*)(cb + d4);
    float4 c0 = *(const float4*)(base);
    float4 c1 = (l >= 1) ? *(const float4*)(base - 2 * DI) : make_float4(0, 0, 0, 0);
    float4 c2 = (l >= 2) ? *(const float4*)(base - 4 * DI) : make_float4(0, 0, 0, 0);
    float m1 = (l >= 1) ? 1.f : 0.f;
    float m2 = (l >= 2) ? 1.f : 0.f;

    float4 o;
    #pragma unroll
    for (int t = 0; t < 4; t++) {
        float w0 = cw[(d4 + t) * 3 + 0], w1 = cw[(d4 + t) * 3 + 1], w2 = cw[(d4 + t) * 3 + 2];
        float b  = ((const float*)&bin)[t];
        float x0 = ((const float*)&c0)[t] + b;
        float x1 = ((const float*)&c1)[t] + b;
        float x2 = ((const float*)&c2)[t] + b;
        float a = fmaf(w2, x0, ((const float*)&cb4)[t]);
        a = fmaf(w1 * m1, x1, a);
        a = fmaf(w0 * m2, x2, a);
        ((float*)&o)[t] = a / (1.f + __expf(-a));
    }
    *(float4*)(u + ((size_t)row * DI + d4)) = o;
}

// ---------------- chunked selective scan + gating, emits bf16 hi/lo ----------
__global__ __launch_bounds__(128)
void scan_kernel(const float* __restrict__ A_log,
                 const float* __restrict__ delta,
                 const float* __restrict__ u,
                 const float* __restrict__ xr,
                 const float* __restrict__ b_in,
                 const float* __restrict__ xp,
                 __nv_bfloat16* __restrict__ gh,
                 __nv_bfloat16* __restrict__ gl)
{
    const int bc = blockIdx.x;
    const int b  = bc / NC;
    const int c  = bc - b * NC;
    const int d  = blockIdx.y * 128 + threadIdx.x;
    const int row0 = b * SEQ + c * CHUNK_T;
    const float bres = b_in[DI + d];

    float Aa[NS], st[NS];
    #pragma unroll
    for (int n = 0; n < NS; n++) {
        Aa[n] = -expf(A_log[d * NS + n]);
        st[n] = 0.f;
    }

    __shared__ float Bs[16][NS];
    __shared__ float Cs[16][NS];

    for (int t0 = 0; t0 < CHUNK_T; t0 += 16) {
        __syncthreads();
        #pragma unroll
        for (int i = 0; i < 4; i++) {
            int e   = threadIdx.x + i * 128;
            int tl  = e >> 5;
            int rem = e & 31;
            float v = xp[(size_t)(row0 + t0 + tl) * XPW + DTR + rem];
            if (rem < NS) Bs[tl][rem]       = v;
            else          Cs[tl][rem - NS]  = v;
        }
        __syncthreads();

        #pragma unroll 4
        for (int tt = 0; tt < 16; tt++) {
            const int row = row0 + t0 + tt;
            float dv = delta[(size_t)row * DI + d];
            float uv = u[(size_t)row * DI + d];
            float rv = xr[(size_t)row * (2 * DI) + DI + d] + bres;
            float du = dv * uv;
            float y  = 0.f;
            #pragma unroll
            for (int n = 0; n < NS; n++) {
                float a = __expf(dv * Aa[n]);
                st[n] = fmaf(a, st[n], du * Bs[tt][n]);
                y     = fmaf(st[n], Cs[tt][n], y);
            }
            float gate = rv / (1.f + __expf(-rv));
            float v = y * gate;
            __nv_bfloat16 h = __float2bfloat16(v);
            size_t idx = (size_t)row * DI + d;
            gh[idx] = h;
            gl[idx] = __float2bfloat16(v - __bfloat162float(h));
        }
    }
}

// ---------------- launch ----------------------------------------------------
extern "C" void kernel_launch(void* const* d_in, const int* in_sizes, int n_in,
                              void* d_out, int out_size)
{
    const float* x      = (const float*)d_in[0];
    const float* W_in   = (const float*)d_in[1];
    const float* b_in   = (const float*)d_in[2];
    const float* conv_w = (const float*)d_in[3];
    const float* conv_b = (const float*)d_in[4];
    const float* W_x    = (const float*)d_in[5];
    const float* W_dt   = (const float*)d_in[6];
    const float* b_dt   = (const float*)d_in[7];
    const float* A_log  = (const float*)d_in[8];
    const float* W_out  = (const float*)d_in[9];
    const float* b_out  = (const float*)d_in[10];
    float* out = (float*)d_out;

    float *xr, *u, *xp, *xpp, *delta, *outp;
    cudaGetSymbolAddress((void**)&xr,    g_xr);
    cudaGetSymbolAddress((void**)&u,     g_u);
    cudaGetSymbolAddress((void**)&xp,    g_xp);
    cudaGetSymbolAddress((void**)&xpp,   g_xpp);
    cudaGetSymbolAddress((void**)&delta, g_delta);
    cudaGetSymbolAddress((void**)&outp,  g_outp);

    __nv_bfloat16 *xh, *xl, *wih, *wil, *gh, *gl, *woh, *wol;
    cudaGetSymbolAddress((void**)&xh,  g_xh);
    cudaGetSymbolAddress((void**)&xl,  g_xl);
    cudaGetSymbolAddress((void**)&wih, g_wih);
    cudaGetSymbolAddress((void**)&wil, g_wil);
    cudaGetSymbolAddress((void**)&gh,  g_gh);
    cudaGetSymbolAddress((void**)&gl,  g_gl);
    cudaGetSymbolAddress((void**)&woh, g_woh);
    cudaGetSymbolAddress((void**)&wol, g_wol);

    static bool attr_done = false;
    if (!attr_done) {
        cudaFuncSetAttribute((const void*)gemm3,
                             cudaFuncAttributeMaxDynamicSharedMemorySize, DSM128);
        attr_done = true;
    }

    // 1) fused bf16 hi/lo splits: x, W_in, W_out in one launch
    fuse_split<<<(QTOT + 255) / 256, 256>>>(x, W_in, W_out,
                                            xh, xl, wih, wil, woh, wol);

    // 2) in_proj: xr_raw[2048,4096] = x @ W_in^T
    gemm3<<<dim3(2 * DI / 128, ROWS / 128, 1), 256, DSM128>>>(
        xh, xl, wih, wil, xr, 2 * DI, DM, DM);

    // 3) depthwise causal conv (+b_in) + silu -> u
    conv_silu<<<(ROWS * DI / 4) / 256, 256>>>(xr, b_in, conv_w, conv_b, u);

    // 4) x_proj split-K (profiler slot 4): partials = u @ W_x^T
    gemm_skinny<<<dim3(ROWS / 16, 4), 256>>>(u, W_x, xpp);
    reduce_xp<<<(ROWS * XPW + 255) / 256, 256>>>(xpp, xp);

    // 6) dt_proj + softplus: delta = softplus(xp[:, :64] @ W_dt^T + b_dt)
    gemm_dt<<<dim3(DI / 64, ROWS / 64), 256>>>(xp, W_dt, b_dt, delta);

    // 7) chunked selective scan + gating -> bf16 hi/lo of y*silu(res)
    scan_kernel<<<dim3(BSZ * NC, DI / 128), 128>>>(A_log, delta, u, xr, b_in, xp, gh, gl);

    // 8) out_proj split-K=2: partials[z] = g @ W_out[:, z*1024:(z+1)*1024]^T
    gemm3<<<dim3(DM / 128, ROWS / 128, 2), 256, DSM128>>>(
        gh, gl, woh, wol, outp, DM, DI, DI / 2);

    // 9) reduce partials + bias -> out
    reduce_out<<<(ROWS * DM / 4 + 255) / 256, 256>>>(outp, b_out, out);
}

// round 14
// speedup vs baseline: 1.1688x; 1.0389x over previous
#include <cuda_runtime.h>
#include <cuda_bf16.h>
#include <mma.h>
#include <math.h>
#include <stdint.h>

using namespace nvcuda;

// Problem constants (fixed shapes from reference setup_inputs)
#define BSZ   2
#define SEQ   1024
#define DM    1024
#define DI    2048
#define NS    16
#define DTR   64
#define ROWS  (BSZ*SEQ)     // 2048
#define CHUNK_T 256
#define NC    (SEQ/CHUNK_T) // 4
#define XPW   96            // dt_rank + 2*n_state
#define SKZ   8             // x_proj split-K factor
#define OKZ   4             // out_proj split-K factor

// ---------------- scratch (device globals; no allocation allowed) ----------
__device__ float g_xr[ROWS * 2 * DI];     // in_proj output (raw)
__device__ float g_u[ROWS * DI];          // conv+silu output
__device__ float g_xp[ROWS * XPW];        // x_proj output (dlt | B | C)
__device__ float g_xpp[SKZ * ROWS * XPW]; // x_proj split-K partials
__device__ float g_delta[ROWS * DI];      // softplus(dt_proj)
__device__ float g_outp[OKZ * ROWS * DM]; // out_proj split-K partials

// bf16 hi/lo split buffers
__device__ __nv_bfloat16 g_xh[ROWS * DM],  g_xl[ROWS * DM];      // x split
__device__ __nv_bfloat16 g_wih[2*DI * DM], g_wil[2*DI * DM];     // W_in split
__device__ __nv_bfloat16 g_gh[ROWS * DI],  g_gl[ROWS * DI];      // gated scan out
__device__ __nv_bfloat16 g_woh[DM * DI],   g_wol[DM * DI];       // W_out split

// ---------------- cp.async helpers ------------------------------------------
__device__ __forceinline__ uint32_t smem_u32(const void* p) {
    uint32_t a;
    asm("{ .reg .u64 t; cvta.to.shared.u64 t, %1; cvt.u32.u64 %0, t; }"
        : "=r"(a) : "l"(p));
    return a;
}
__device__ __forceinline__ void cp16(uint32_t dst, const void* src) {
    asm volatile("cp.async.cg.shared.global [%0], [%1], 16;" :: "r"(dst), "l"(src));
}
#define CP_COMMIT() asm volatile("cp.async.commit_group;" ::: "memory")
#define CP_WAIT(n)  asm volatile("cp.async.wait_group %0;" :: "n"(n) : "memory")

// ---------------- fused bf16 hi/lo split (x, W_in, W_out in one launch) ------
#define QX  (ROWS * DM / 4)
#define QWI (2 * DI * DM / 4)
#define QWO (DM * DI / 4)
#define QTOT (QX + QWI + QWO)

__global__ __launch_bounds__(256)
void fuse_split(const float* __restrict__ x,
                const float* __restrict__ Wi,
                const float* __restrict__ Wo,
                __nv_bfloat16* __restrict__ xh,  __nv_bfloat16* __restrict__ xl,
                __nv_bfloat16* __restrict__ wih, __nv_bfloat16* __restrict__ wil,
                __nv_bfloat16* __restrict__ woh, __nv_bfloat16* __restrict__ wol)
{
    int q = blockIdx.x * blockDim.x + threadIdx.x;
    if (q >= QTOT) return;

    const float* src;
    __nv_bfloat16 *dh, *dl;
    int local;
    if (q < QX)            { src = x;  dh = xh;  dl = xl;  local = q; }
    else if (q < QX + QWI) { src = Wi; dh = wih; dl = wil; local = q - QX; }
    else                   { src = Wo; dh = woh; dl = wol; local = q - QX - QWI; }

    float4 v = *(const float4*)(src + (size_t)local * 4);
    float f[4] = {v.x, v.y, v.z, v.w};
    __nv_bfloat16 h[4], l[4];
    #pragma unroll
    for (int t = 0; t < 4; t++) {
        h[t] = __float2bfloat16(f[t]);
        l[t] = __float2bfloat16(f[t] - __bfloat162float(h[t]));
    }
    __nv_bfloat162* ph = (__nv_bfloat162*)(dh + (size_t)local * 4);
    __nv_bfloat162* pl = (__nv_bfloat162*)(dl + (size_t)local * 4);
    ph[0] = __nv_bfloat162{h[0], h[1]};
    ph[1] = __nv_bfloat162{h[2], h[3]};
    pl[0] = __nv_bfloat162{l[0], l[1]};
    pl[1] = __nv_bfloat162{l[2], l[3]};
}

// ============ bf16x3 wmma GEMM, 2-stage cp.async, 2 CTAs/SM, split-K =========
// C[z][M,N] = A[M, z*Kslice : (z+1)*Kslice] @ W[N, same]^T.
// Block tile 128x128, BK=32, 256 thr (8 warps, 4Mx2N), warp tile 32x64.
#define BKP 40
extern __shared__ char dsm[];

__global__ void __launch_bounds__(256, 2)
gemm3(const __nv_bfloat16* __restrict__ Ah, const __nv_bfloat16* __restrict__ Al,
      const __nv_bfloat16* __restrict__ Bh, const __nv_bfloat16* __restrict__ Bl,
      float* __restrict__ C, int N, int Kstride, int Kslice)
{
    constexpr int OFF_AL   = 128 * BKP;
    constexpr int OFF_BH   = 256 * BKP;
    constexpr int OFF_BL   = 384 * BKP;
    constexpr int STAGE_BY = 512 * BKP * 2;             // 40960 B

    const int tid = threadIdx.x;
    const int wid = tid >> 5;
    const int wr  = wid & 3;
    const int wc  = wid >> 2;
    const int m0  = blockIdx.y * 128;
    const int n0  = blockIdx.x * 128;
    const int kbase = blockIdx.z * Kslice;
    float* Cz = C + (size_t)blockIdx.z * ROWS * N;

    const uint32_t sb0 = smem_u32(dsm);

    wmma::fragment<wmma::accumulator, 16, 16, 16, float> acc[2][4];
    #pragma unroll
    for (int i = 0; i < 2; i++)
        #pragma unroll
        for (int j = 0; j < 4; j++) wmma::fill_fragment(acc[i][j], 0.0f);

    auto fill = [&](int buf, int k0) {
        uint32_t sb = sb0 + buf * STAGE_BY;
        #pragma unroll
        for (int j = 0; j < 2; j++) {
            int id = tid + j * 256;
            int r = id >> 2, c = id & 3;
            const size_t ga = (size_t)(m0 + r) * Kstride + kbase + k0 + c * 8;
            const size_t gb = (size_t)(n0 + r) * Kstride + kbase + k0 + c * 8;
            uint32_t so = (uint32_t)(r * BKP + c * 8) * 2;
            cp16(sb + so, Ah + ga);
            cp16(sb + OFF_AL * 2 + so, Al + ga);
            cp16(sb + OFF_BH * 2 + so, Bh + gb);
            cp16(sb + OFF_BL * 2 + so, Bl + gb);
        }
    };

    const int S = Kslice >> 5;
    fill(0, 0);
    CP_COMMIT();

    for (int s = 0; s < S; s++) {
        const int cur = s & 1;
        if (s + 1 < S) { fill(cur ^ 1, (s + 1) << 5); CP_COMMIT(); CP_WAIT(1); }
        else           { CP_WAIT(0); }
        __syncthreads();

        const __nv_bfloat16* Sm = (const __nv_bfloat16*)(dsm + cur * STAGE_BY);

        #pragma unroll
        for (int kk = 0; kk < 32; kk += 16) {
            wmma::fragment<wmma::matrix_a, 16, 16, 16, __nv_bfloat16, wmma::row_major> ah[2], al[2];
            #pragma unroll
            for (int i = 0; i < 2; i++) {
                int r = (wr * 32 + i * 16) * BKP + kk;
                wmma::load_matrix_sync(ah[i], Sm + r, BKP);
                wmma::load_matrix_sync(al[i], Sm + OFF_AL + r, BKP);
            }
            #pragma unroll
            for (int j = 0; j < 4; j++) {
                wmma::fragment<wmma::matrix_b, 16, 16, 16, __nv_bfloat16, wmma::col_major> bh, bl;
                int r = (wc * 64 + j * 16) * BKP + kk;
                wmma::load_matrix_sync(bh, Sm + OFF_BH + r, BKP);
                wmma::load_matrix_sync(bl, Sm + OFF_BL + r, BKP);
                #pragma unroll
                for (int i = 0; i < 2; i++) {
                    wmma::mma_sync(acc[i][j], ah[i], bh, acc[i][j]);
                    wmma::mma_sync(acc[i][j], ah[i], bl, acc[i][j]);
                    wmma::mma_sync(acc[i][j], al[i], bh, acc[i][j]);
                }
            }
        }
        __syncthreads();
    }

    #pragma unroll
    for (int i = 0; i < 2; i++)
        #pragma unroll
        for (int j = 0; j < 4; j++) {
            float* p = Cz + (size_t)(m0 + wr * 32 + i * 16) * N + n0 + wc * 64 + j * 16;
            wmma::store_matrix_sync(p, acc[i][j], N, wmma::mem_row_major);
        }
}

#define DSM128 (2 * 512 * BKP * 2)   // 81920 B

// ---------------- out_proj reduce (split-K sum) + bias -----------------------
__global__ __launch_bounds__(256)
void reduce_out(const float* __restrict__ P, const float* __restrict__ bias,
                float* __restrict__ out)
{
    int q = blockIdx.x * blockDim.x + threadIdx.x;   // quads over ROWS*DM/4
    if (q >= ROWS * DM / 4) return;
    int col4 = (q << 2) & (DM - 1);
    float4 c = *(const float4*)(bias + col4);
    float4 o = c;
    #pragma unroll
    for (int z = 0; z < OKZ; z++) {
        float4 a = *(const float4*)(P + (size_t)z * ROWS * DM + (size_t)q * 4);
        o.x += a.x; o.y += a.y; o.z += a.z; o.w += a.w;
    }
    *(float4*)(out + (size_t)q * 4) = o;
}

// ---------------- dt_proj: delta = softplus(xp[:, :64] @ W_dt^T + b_dt) ------
__global__ __launch_bounds__(256)
void gemm_dt(const float* __restrict__ A,   // xp, lda=XPW
             const float* __restrict__ W,   // W_dt [DI, 64]
             const float* __restrict__ bias,
             float* __restrict__ C)         // delta [ROWS, DI]
{
    __shared__ float As[64][65];
    __shared__ float Ws[64][65];

    const int tid = threadIdx.x;
    const int m0 = blockIdx.y * 64;
    const int n0 = blockIdx.x * 64;

    #pragma unroll
    for (int j = 0; j < 4; j++) {
        int id = tid + j * 256;
        int r = id >> 4, c4 = (id & 15) << 2;
        float4 va = *(const float4*)(A + (size_t)(m0 + r) * XPW + c4);
        As[c4 + 0][r] = va.x; As[c4 + 1][r] = va.y;
        As[c4 + 2][r] = va.z; As[c4 + 3][r] = va.w;
        float4 vw = *(const float4*)(W + (size_t)(n0 + r) * DTR + c4);
        Ws[c4 + 0][r] = vw.x; Ws[c4 + 1][r] = vw.y;
        Ws[c4 + 2][r] = vw.z; Ws[c4 + 3][r] = vw.w;
    }
    __syncthreads();

    const int tx = tid & 15;
    const int ty = tid >> 4;
    float acc[4][4];
    #pragma unroll
    for (int i = 0; i < 4; i++)
        #pragma unroll
        for (int j = 0; j < 4; j++) acc[i][j] = 0.f;

    #pragma unroll 8
    for (int k = 0; k < 64; k++) {
        float a[4], b[4];
        #pragma unroll
        for (int i = 0; i < 4; i++) a[i] = As[k][ty * 4 + i];
        #pragma unroll
        for (int j = 0; j < 4; j++) b[j] = Ws[k][tx * 4 + j];
        #pragma unroll
        for (int i = 0; i < 4; i++)
            #pragma unroll
            for (int j = 0; j < 4; j++)
                acc[i][j] = fmaf(a[i], b[j], acc[i][j]);
    }

    #pragma unroll
    for (int i = 0; i < 4; i++) {
        int m = m0 + ty * 4 + i;
        #pragma unroll
        for (int j = 0; j < 4; j++) {
            int n = n0 + tx * 4 + j;
            float v = acc[i][j] + bias[n];
            v = fmaxf(v, 0.f) + log1pf(expf(-fabsf(v)));
            C[(size_t)m * DI + n] = v;
        }
    }
}

// ---------------- x_proj split-K: partials[z] = u @ W_x^T (K slice) ----------
// Tile 64 rows x 96 cols, 256 thr: thread = 8 rows x 3 cols.
// A-reads: LDS.128 broadcast (lanes share ty); Ws scalar stride-3 (conflict-free).
__global__ __launch_bounds__(256)
void gemm_skinny(const float* __restrict__ A,
                 const float* __restrict__ W,
                 float* __restrict__ P)
{
    __shared__ __align__(16) float As[32][68];
    __shared__ float Ws[32][100];

    const int tid = threadIdx.x;
    const int tx = tid & 31;       // cols tx*3 .. +2
    const int ty = tid >> 5;       // rows ty*8 .. +7
    const int m0 = blockIdx.x * 64;
    const int kb = blockIdx.y * (DI / SKZ);     // 256-wide K slice
    float* C = P + (size_t)blockIdx.y * ROWS * XPW;

    float acc[8][3];
    #pragma unroll
    for (int i = 0; i < 8; i++)
        #pragma unroll
        for (int j = 0; j < 3; j++) acc[i][j] = 0.f;

    for (int k0 = kb; k0 < kb + DI / SKZ; k0 += 32) {
        #pragma unroll
        for (int i = 0; i < 2; i++) {            // A tile 64x32 = 512 float4
            int f = tid + i * 256;
            int r = f >> 3, kq = (f & 7) << 2;
            float4 v = *(const float4*)(A + (size_t)(m0 + r) * DI + k0 + kq);
            As[kq + 0][r] = v.x; As[kq + 1][r] = v.y;
            As[kq + 2][r] = v.z; As[kq + 3][r] = v.w;
        }
        #pragma unroll
        for (int i = 0; i < 3; i++) {            // W tile 96x32 = 768 float4
            int f = tid + i * 256;
            int r = f >> 3, kq = (f & 7) << 2;
            float4 v = *(const float4*)(W + (size_t)r * DI + k0 + kq);
            Ws[kq + 0][r] = v.x; Ws[kq + 1][r] = v.y;
            Ws[kq + 2][r] = v.z; Ws[kq + 3][r] = v.w;
        }
        __syncthreads();

        #pragma unroll
        for (int k = 0; k < 32; k++) {
            float a[8];
            *(float4*)(a)     = *(const float4*)&As[k][ty * 8];
            *(float4*)(a + 4) = *(const float4*)&As[k][ty * 8 + 4];
            float b0 = Ws[k][tx * 3 + 0], b1 = Ws[k][tx * 3 + 1], b2 = Ws[k][tx * 3 + 2];
            #pragma unroll
            for (int i = 0; i < 8; i++) {
                acc[i][0] = fmaf(a[i], b0, acc[i][0]);
                acc[i][1] = fmaf(a[i], b1, acc[i][1]);
                acc[i][2] = fmaf(a[i], b2, acc[i][2]);
            }
        }
        __syncthreads();
    }

    #pragma unroll
    for (int i = 0; i < 8; i++)
        #pragma unroll
        for (int j = 0; j < 3; j++)
            C[(size_t)(m0 + ty * 8 + i) * XPW + tx * 3 + j] = acc[i][j];
}

__global__ __launch_bounds__(256)
void reduce_xp(const float* __restrict__ P, float* __restrict__ xp)
{
    int i = blockIdx.x * blockDim.x + threadIdx.x;
    if (i >= ROWS * XPW) return;
    float s = 0.f;
    #pragma unroll
    for (int z = 0; z < SKZ; z++) s += P[i + (size_t)z * ROWS * XPW];
    xp[i] = s;
}

// ---------------- causal depthwise conv (k=3) + SiLU, float4 -----------------
__global__ __launch_bounds__(256)
void conv_silu(const float* __restrict__ xr,
               const float* __restrict__ b_in,
               const float* __restrict__ cw,
               const float* __restrict__ cb,
               float* __restrict__ u)
{
    int q   = blockIdx.x * blockDim.x + threadIdx.x;
    int d4  = (q << 2) & (DI - 1);
    int row = q >> 9;
    int l   = row & (SEQ - 1);
    const float* base = xr + (size_t)row * (2 * DI) + d4;
    float4 bin = *(const float4*)(b_in + d4);
    float4 cb4 = *(const float4*)(cb + d4);
    float4 c0 = *(const float4*)(base);
    float4 c1 = (l >= 1) ? *(const float4*)(base - 2 * DI) : make_float4(0, 0, 0, 0);
    float4 c2 = (l >= 2) ? *(const float4*)(base - 4 * DI) : make_float4(0, 0, 0, 0);
    float m1 = (l >= 1) ? 1.f : 0.f;
    float m2 = (l >= 2) ? 1.f : 0.f;

    float4 o;
    #pragma unroll
    for (int t = 0; t < 4; t++) {
        float w0 = cw[(d4 + t) * 3 + 0], w1 = cw[(d4 + t) * 3 + 1], w2 = cw[(d4 + t) * 3 + 2];
        float b  = ((const float*)&bin)[t];
        float x0 = ((const float*)&c0)[t] + b;
        float x1 = ((const float*)&c1)[t] + b;
        float x2 = ((const float*)&c2)[t] + b;
        float a = fmaf(w2, x0, ((const float*)&cb4)[t]);
        a = fmaf(w1 * m1, x1, a);
        a = fmaf(w0 * m2, x2, a);
        ((float*)&o)[t] = a / (1.f + __expf(-a));
    }
    *(float4*)(u + ((size_t)row * DI + d4)) = o;
}

// ---------------- chunked selective scan + gating, emits bf16 hi/lo ----------
__global__ __launch_bounds__(128)
void scan_kernel(const float* __restrict__ A_log,
                 const float* __restrict__ delta,
                 const float* __restrict__ u,
                 const float* __restrict__ xr,
                 const float* __restrict__ b_in,
                 const float* __restrict__ xp,
                 __nv_bfloat16* __restrict__ gh,
                 __nv_bfloat16* __restrict__ gl)
{
    const int bc = blockIdx.x;
    const int b  = bc / NC;
    const int c  = bc - b * NC;
    const int d  = blockIdx.y * 128 + threadIdx.x;
    const int row0 = b * SEQ + c * CHUNK_T;
    const float bres = b_in[DI + d];

    float Aa[NS], st[NS];
    #pragma unroll
    for (int n = 0; n < NS; n++) {
        Aa[n] = -expf(A_log[d * NS + n]);
        st[n] = 0.f;
    }

    __shared__ float Bs[16][NS];
    __shared__ float Cs[16][NS];

    for (int t0 = 0; t0 < CHUNK_T; t0 += 16) {
        __syncthreads();
        #pragma unroll
        for (int i = 0; i < 4; i++) {
            int e   = threadIdx.x + i * 128;
            int tl  = e >> 5;
            int rem = e & 31;
            float v = xp[(size_t)(row0 + t0 + tl) * XPW + DTR + rem];
            if (rem < NS) Bs[tl][rem]       = v;
            else          Cs[tl][rem - NS]  = v;
        }
        __syncthreads();

        #pragma unroll 4
        for (int tt = 0; tt < 16; tt++) {
            const int row = row0 + t0 + tt;
            float dv = delta[(size_t)row * DI + d];
            float uv = u[(size_t)row * DI + d];
            float rv = xr[(size_t)row * (2 * DI) + DI + d] + bres;
            float du = dv * uv;
            float y  = 0.f;
            #pragma unroll
            for (int n = 0; n < NS; n++) {
                float a = __expf(dv * Aa[n]);
                st[n] = fmaf(a, st[n], du * Bs[tt][n]);
                y     = fmaf(st[n], Cs[tt][n], y);
            }
            float gate = rv / (1.f + __expf(-rv));
            float v = y * gate;
            __nv_bfloat16 h = __float2bfloat16(v);
            size_t idx = (size_t)row * DI + d;
            gh[idx] = h;
            gl[idx] = __float2bfloat16(v - __bfloat162float(h));
        }
    }
}

// ---------------- launch ----------------------------------------------------
extern "C" void kernel_launch(void* const* d_in, const int* in_sizes, int n_in,
                              void* d_out, int out_size)
{
    const float* x      = (const float*)d_in[0];
    const float* W_in   = (const float*)d_in[1];
    const float* b_in   = (const float*)d_in[2];
    const float* conv_w = (const float*)d_in[3];
    const float* conv_b = (const float*)d_in[4];
    const float* W_x    = (const float*)d_in[5];
    const float* W_dt   = (const float*)d_in[6];
    const float* b_dt   = (const float*)d_in[7];
    const float* A_log  = (const float*)d_in[8];
    const float* W_out  = (const float*)d_in[9];
    const float* b_out  = (const float*)d_in[10];
    float* out = (float*)d_out;

    float *xr, *u, *xp, *xpp, *delta, *outp;
    cudaGetSymbolAddress((void**)&xr,    g_xr);
    cudaGetSymbolAddress((void**)&u,     g_u);
    cudaGetSymbolAddress((void**)&xp,    g_xp);
    cudaGetSymbolAddress((void**)&xpp,   g_xpp);
    cudaGetSymbolAddress((void**)&delta, g_delta);
    cudaGetSymbolAddress((void**)&outp,  g_outp);

    __nv_bfloat16 *xh, *xl, *wih, *wil, *gh, *gl, *woh, *wol;
    cudaGetSymbolAddress((void**)&xh,  g_xh);
    cudaGetSymbolAddress((void**)&xl,  g_xl);
    cudaGetSymbolAddress((void**)&wih, g_wih);
    cudaGetSymbolAddress((void**)&wil, g_wil);
    cudaGetSymbolAddress((void**)&gh,  g_gh);
    cudaGetSymbolAddress((void**)&gl,  g_gl);
    cudaGetSymbolAddress((void**)&woh, g_woh);
    cudaGetSymbolAddress((void**)&wol, g_wol);

    static bool attr_done = false;
    if (!attr_done) {
        cudaFuncSetAttribute((const void*)gemm3,
                             cudaFuncAttributeMaxDynamicSharedMemorySize, DSM128);
        attr_done = true;
    }

    // 1) fused bf16 hi/lo splits: x, W_in, W_out in one launch
    fuse_split<<<(QTOT + 255) / 256, 256>>>(x, W_in, W_out,
                                            xh, xl, wih, wil, woh, wol);

    // 2) in_proj: xr_raw[2048,4096] = x @ W_in^T
    gemm3<<<dim3(2 * DI / 128, ROWS / 128, 1), 256, DSM128>>>(
        xh, xl, wih, wil, xr, 2 * DI, DM, DM);

    // 3) depthwise causal conv (+b_in) + silu -> u
    conv_silu<<<(ROWS * DI / 4) / 256, 256>>>(xr, b_in, conv_w, conv_b, u);

    // 4) x_proj split-K=8 (profiler slot 4): partials = u @ W_x^T
    gemm_skinny<<<dim3(ROWS / 64, SKZ), 256>>>(u, W_x, xpp);
    reduce_xp<<<(ROWS * XPW + 255) / 256, 256>>>(xpp, xp);

    // 6) dt_proj + softplus: delta = softplus(xp[:, :64] @ W_dt^T + b_dt)
    gemm_dt<<<dim3(DI / 64, ROWS / 64), 256>>>(xp, W_dt, b_dt, delta);

    // 7) chunked selective scan + gating -> bf16 hi/lo of y*silu(res)
    scan_kernel<<<dim3(BSZ * NC, DI / 128), 128>>>(A_log, delta, u, xr, b_in, xp, gh, gl);

    // 8) out_proj split-K=4: partials[z] = g @ W_out[:, z*512:(z+1)*512]^T
    gemm3<<<dim3(DM / 128, ROWS / 128, OKZ), 256, DSM128>>>(
        gh, gl, woh, wol, outp, DM, DI, DI / OKZ);

    // 9) reduce partials + bias -> out
    reduce_out<<<(ROWS * DM / 4 + 255) / 256, 256>>>(outp, b_out, out);
}